// round 8
// baseline (speedup 1.0000x reference)
#include <cuda_runtime.h>
#include <math.h>

#define IMG_H 512
#define IMG_W 512
#define NB    64
#define NPIX  (IMG_H * IMG_W)
#define NPEL  (NPIX * 3)
#define RBLK  32
#define ROWF  (IMG_W * 3)

// scratch in RGBX float4 layout (16 B/pixel, aligned -> 1 LDG.128 per tap)
__device__ float4 g_scratch4[(size_t)NB * NPIX];
__device__ float  g_partial0[NB * RBLK];
__device__ float  g_partial1[NB * RBLK];

struct F3 { float x, y, z; };

__device__ __forceinline__ float inline_mean(const float* __restrict__ part, int b)
{
    float s = 0.f;
    #pragma unroll
    for (int i = 0; i < RBLK; i++) s += part[b * RBLK + i];
    return s * (1.0f / (float)NPEL);
}

// ============================ HWC taps (input image, pass1) ================
__device__ __forceinline__ F3 bilin_h(const float* __restrict__ img, float xi, int y)
{
    float x0f = floorf(xi);
    float wx  = xi - x0f;
    float w0  = 1.f - wx;
    int   x0  = (int)x0f;
    const float* row = img + (size_t)y * ROWF;
    F3 r;
    if (x0 >= 0 && x0 < IMG_W - 1) {
        const float* p = row + x0 * 3;
        r.x = w0 * p[0] + wx * p[3];
        r.y = w0 * p[1] + wx * p[4];
        r.z = w0 * p[2] + wx * p[5];
    } else {
        bool v0 = (x0 >= 0)  && (x0 <= IMG_W - 1);
        bool v1 = (x0 >= -1) && (x0 <= IMG_W - 2);
        int xc0 = min(max(x0,     0), IMG_W - 1);
        int xc1 = min(max(x0 + 1, 0), IMG_W - 1);
        const float* p0 = row + xc0 * 3;
        const float* p1 = row + xc1 * 3;
        float a0 = v0 ? p0[0] : 0.5f, a1 = v0 ? p0[1] : 0.5f, a2 = v0 ? p0[2] : 0.5f;
        float b0 = v1 ? p1[0] : 0.5f, b1 = v1 ? p1[1] : 0.5f, b2 = v1 ? p1[2] : 0.5f;
        r.x = w0 * a0 + wx * b0;
        r.y = w0 * a1 + wx * b1;
        r.z = w0 * a2 + wx * b2;
    }
    return r;
}

__device__ __forceinline__ F3 bilin_v(const float* __restrict__ img, float yi, int x)
{
    float y0f = floorf(yi);
    float wy  = yi - y0f;
    float w0  = 1.f - wy;
    int   y0  = (int)y0f;
    F3 r;
    if (y0 >= 0 && y0 < IMG_H - 1) {
        const float* p = img + ((size_t)y0 * IMG_W + x) * 3;
        const float* q = p + ROWF;
        r.x = w0 * p[0] + wy * q[0];
        r.y = w0 * p[1] + wy * q[1];
        r.z = w0 * p[2] + wy * q[2];
    } else {
        bool v0 = (y0 >= 0)  && (y0 <= IMG_H - 1);
        bool v1 = (y0 >= -1) && (y0 <= IMG_H - 2);
        int yc0 = min(max(y0,     0), IMG_H - 1);
        int yc1 = min(max(y0 + 1, 0), IMG_H - 1);
        const float* p0 = img + ((size_t)yc0 * IMG_W + x) * 3;
        const float* p1 = img + ((size_t)yc1 * IMG_W + x) * 3;
        float a0 = v0 ? p0[0] : 0.5f, a1 = v0 ? p0[1] : 0.5f, a2 = v0 ? p0[2] : 0.5f;
        float b0 = v1 ? p1[0] : 0.5f, b1 = v1 ? p1[1] : 0.5f, b2 = v1 ? p1[2] : 0.5f;
        r.x = w0 * a0 + wy * b0;
        r.y = w0 * a1 + wy * b1;
        r.z = w0 * a2 + wy * b2;
    }
    return r;
}

__device__ __forceinline__ F3 bilin4(const float* __restrict__ img, float xi, float yi)
{
    float x0f = floorf(xi), y0f = floorf(yi);
    float wx = xi - x0f,    wy = yi - y0f;
    int   x0 = (int)x0f,    y0 = (int)y0f;
    float w00 = (1.f - wx) * (1.f - wy);
    float w10 = wx * (1.f - wy);
    float w01 = (1.f - wx) * wy;
    float w11 = wx * wy;
    F3 r;
    if (x0 >= 0 && x0 < IMG_W - 1 && y0 >= 0 && y0 < IMG_H - 1) {
        const float* p = img + ((size_t)y0 * IMG_W + x0) * 3;
        const float* q = p + ROWF;
        r.x = w00 * p[0] + w10 * p[3] + w01 * q[0] + w11 * q[3];
        r.y = w00 * p[1] + w10 * p[4] + w01 * q[1] + w11 * q[4];
        r.z = w00 * p[2] + w10 * p[5] + w01 * q[2] + w11 * q[5];
    } else {
        bool vx0 = (x0 >= 0)  && (x0 <= IMG_W - 1);
        bool vx1 = (x0 >= -1) && (x0 <= IMG_W - 2);
        bool vy0 = (y0 >= 0)  && (y0 <= IMG_H - 1);
        bool vy1 = (y0 >= -1) && (y0 <= IMG_H - 2);
        int xc0 = min(max(x0,     0), IMG_W - 1);
        int xc1 = min(max(x0 + 1, 0), IMG_W - 1);
        int yc0 = min(max(y0,     0), IMG_H - 1);
        int yc1 = min(max(y0 + 1, 0), IMG_H - 1);
        const float* p00 = img + ((size_t)yc0 * IMG_W + xc0) * 3;
        const float* p10 = img + ((size_t)yc0 * IMG_W + xc1) * 3;
        const float* p01 = img + ((size_t)yc1 * IMG_W + xc0) * 3;
        const float* p11 = img + ((size_t)yc1 * IMG_W + xc1) * 3;
        bool v00 = vx0 && vy0, v10 = vx1 && vy0, v01 = vx0 && vy1, v11 = vx1 && vy1;
        r.x = w00 * (v00 ? p00[0] : 0.5f) + w10 * (v10 ? p10[0] : 0.5f)
            + w01 * (v01 ? p01[0] : 0.5f) + w11 * (v11 ? p11[0] : 0.5f);
        r.y = w00 * (v00 ? p00[1] : 0.5f) + w10 * (v10 ? p10[1] : 0.5f)
            + w01 * (v01 ? p01[1] : 0.5f) + w11 * (v11 ? p11[1] : 0.5f);
        r.z = w00 * (v00 ? p00[2] : 0.5f) + w10 * (v10 ? p10[2] : 0.5f)
            + w01 * (v01 ? p01[2] : 0.5f) + w11 * (v11 ? p11[2] : 0.5f);
    }
    return r;
}

__device__ __forceinline__ F3 sharp3x3(const float* __restrict__ img,
                                       float f, int x, int y)
{
    F3 r;
    if (x >= 1 && x < IMG_W - 1 && y >= 1 && y < IMG_H - 1) {
        const float* pc = img + ((size_t)y * IMG_W + x) * 3;
        const float* pm = pc - ROWF;
        const float* pp = pc + ROWF;
        float v0 = pc[0], v1 = pc[1], v2 = pc[2];
        float s0 = pm[-3] + pm[0] + pm[3] + pc[-3] + pc[3] + pp[-3] + pp[0] + pp[3];
        float s1 = pm[-2] + pm[1] + pm[4] + pc[-2] + pc[4] + pp[-2] + pp[1] + pp[4];
        float s2 = pm[-1] + pm[2] + pm[5] + pc[-1] + pc[5] + pp[-1] + pp[2] + pp[5];
        s0 = (s0 + 5.f * v0) * (1.f / 13.f);
        s1 = (s1 + 5.f * v1) * (1.f / 13.f);
        s2 = (s2 + 5.f * v2) * (1.f / 13.f);
        r.x = fminf(fmaxf(s0 + f * (v0 - s0), 0.f), 1.f);
        r.y = fminf(fmaxf(s1 + f * (v1 - s1), 0.f), 1.f);
        r.z = fminf(fmaxf(s2 + f * (v2 - s2), 0.f), 1.f);
    } else {
        const float* p = img + ((size_t)y * IMG_W + x) * 3;
        float v0 = p[0], v1 = p[1], v2 = p[2];
        float s0 = 0.f, s1 = 0.f, s2 = 0.f;
        #pragma unroll
        for (int dy = -1; dy <= 1; dy++) {
            int yy = min(max(y + dy, 0), IMG_H - 1);
            #pragma unroll
            for (int dx = -1; dx <= 1; dx++) {
                int xx = min(max(x + dx, 0), IMG_W - 1);
                float k = (dx == 0 && dy == 0) ? (5.0f/13.0f) : (1.0f/13.0f);
                const float* q = img + ((size_t)yy * IMG_W + xx) * 3;
                s0 += k * q[0]; s1 += k * q[1]; s2 += k * q[2];
            }
        }
        r.x = fminf(fmaxf(s0 + f * (v0 - s0), 0.f), 1.f);
        r.y = fminf(fmaxf(s1 + f * (v1 - s1), 0.f), 1.f);
        r.z = fminf(fmaxf(s2 + f * (v2 - s2), 0.f), 1.f);
    }
    return r;
}

__device__ __forceinline__ F3 apply_gather_hwc(const float* __restrict__ img,
                                               int op, float s, int x, int y)
{
    const float cx = (IMG_W - 1) * 0.5f, cy = (IMG_H - 1) * 0.5f;
    const float xf = (float)x - cx, yf = (float)y - cy;
    if (op == 0) {
        float th = s * 0.2617993877991494f;
        float co = cosf(th), si = sinf(th);
        return bilin4(img, co * xf + si * yf + cx, -si * xf + co * yf + cy);
    }
    if (op == 1) return bilin_h(img, xf + (-s * 0.15f) * yf + cx, y);
    if (op == 2) return bilin_v(img, yf + (-s * 0.15f) * xf + cy, x);
    if (op == 3) return bilin_h(img, xf + (-s * 0.15f * (float)IMG_W) + cx, y);
    if (op == 4) return bilin_v(img, yf + (-s * 0.15f * (float)IMG_H) + cy, x);
    float f = (s > 0.f) ? 1.45f : (1.0f / 1.45f);
    return sharp3x3(img, f, x, y);
}

// ====================== RGBX float4 taps (scratch, pass2) ==================
__device__ __forceinline__ F3 bilin_h4x(const float4* __restrict__ img, float xi, int y)
{
    float x0f = floorf(xi);
    float wx  = xi - x0f;
    float w0  = 1.f - wx;
    int   x0  = (int)x0f;
    const float4* row = img + (size_t)y * IMG_W;
    float4 a, b;
    if (x0 >= 0 && x0 < IMG_W - 1) {
        a = row[x0]; b = row[x0 + 1];
    } else {
        bool v0 = (x0 >= 0)  && (x0 <= IMG_W - 1);
        bool v1 = (x0 >= -1) && (x0 <= IMG_W - 2);
        a = row[min(max(x0,     0), IMG_W - 1)];
        b = row[min(max(x0 + 1, 0), IMG_W - 1)];
        if (!v0) a = make_float4(0.5f, 0.5f, 0.5f, 0.5f);
        if (!v1) b = make_float4(0.5f, 0.5f, 0.5f, 0.5f);
    }
    F3 r;
    r.x = w0 * a.x + wx * b.x;
    r.y = w0 * a.y + wx * b.y;
    r.z = w0 * a.z + wx * b.z;
    return r;
}

__device__ __forceinline__ F3 bilin_v4x(const float4* __restrict__ img, float yi, int x)
{
    float y0f = floorf(yi);
    float wy  = yi - y0f;
    float w0  = 1.f - wy;
    int   y0  = (int)y0f;
    float4 a, b;
    if (y0 >= 0 && y0 < IMG_H - 1) {
        a = img[(size_t)y0 * IMG_W + x];
        b = img[(size_t)(y0 + 1) * IMG_W + x];
    } else {
        bool v0 = (y0 >= 0)  && (y0 <= IMG_H - 1);
        bool v1 = (y0 >= -1) && (y0 <= IMG_H - 2);
        a = img[(size_t)min(max(y0,     0), IMG_H - 1) * IMG_W + x];
        b = img[(size_t)min(max(y0 + 1, 0), IMG_H - 1) * IMG_W + x];
        if (!v0) a = make_float4(0.5f, 0.5f, 0.5f, 0.5f);
        if (!v1) b = make_float4(0.5f, 0.5f, 0.5f, 0.5f);
    }
    F3 r;
    r.x = w0 * a.x + wy * b.x;
    r.y = w0 * a.y + wy * b.y;
    r.z = w0 * a.z + wy * b.z;
    return r;
}

__device__ __forceinline__ F3 bilin44x(const float4* __restrict__ img, float xi, float yi)
{
    float x0f = floorf(xi), y0f = floorf(yi);
    float wx = xi - x0f,    wy = yi - y0f;
    int   x0 = (int)x0f,    y0 = (int)y0f;
    float w00 = (1.f - wx) * (1.f - wy);
    float w10 = wx * (1.f - wy);
    float w01 = (1.f - wx) * wy;
    float w11 = wx * wy;
    float4 p00, p10, p01, p11;
    if (x0 >= 0 && x0 < IMG_W - 1 && y0 >= 0 && y0 < IMG_H - 1) {
        const float4* p = img + (size_t)y0 * IMG_W + x0;
        p00 = p[0]; p10 = p[1]; p01 = p[IMG_W]; p11 = p[IMG_W + 1];
    } else {
        bool vx0 = (x0 >= 0)  && (x0 <= IMG_W - 1);
        bool vx1 = (x0 >= -1) && (x0 <= IMG_W - 2);
        bool vy0 = (y0 >= 0)  && (y0 <= IMG_H - 1);
        bool vy1 = (y0 >= -1) && (y0 <= IMG_H - 2);
        int xc0 = min(max(x0,     0), IMG_W - 1);
        int xc1 = min(max(x0 + 1, 0), IMG_W - 1);
        int yc0 = min(max(y0,     0), IMG_H - 1);
        int yc1 = min(max(y0 + 1, 0), IMG_H - 1);
        float4 fill = make_float4(0.5f, 0.5f, 0.5f, 0.5f);
        p00 = (vx0 && vy0) ? img[(size_t)yc0 * IMG_W + xc0] : fill;
        p10 = (vx1 && vy0) ? img[(size_t)yc0 * IMG_W + xc1] : fill;
        p01 = (vx0 && vy1) ? img[(size_t)yc1 * IMG_W + xc0] : fill;
        p11 = (vx1 && vy1) ? img[(size_t)yc1 * IMG_W + xc1] : fill;
    }
    F3 r;
    r.x = w00 * p00.x + w10 * p10.x + w01 * p01.x + w11 * p11.x;
    r.y = w00 * p00.y + w10 * p10.y + w01 * p01.y + w11 * p11.y;
    r.z = w00 * p00.z + w10 * p10.z + w01 * p01.z + w11 * p11.z;
    return r;
}

__device__ __forceinline__ F3 sharp3x34x(const float4* __restrict__ img,
                                         float f, int x, int y)
{
    float s0 = 0.f, s1 = 0.f, s2 = 0.f;
    float4 c;
    if (x >= 1 && x < IMG_W - 1 && y >= 1 && y < IMG_H - 1) {
        const float4* pc = img + (size_t)y * IMG_W + x;
        const float4* pm = pc - IMG_W;
        const float4* pp = pc + IMG_W;
        c = pc[0];
        float4 t;
        t = pm[-1]; s0 += t.x; s1 += t.y; s2 += t.z;
        t = pm[ 0]; s0 += t.x; s1 += t.y; s2 += t.z;
        t = pm[ 1]; s0 += t.x; s1 += t.y; s2 += t.z;
        t = pc[-1]; s0 += t.x; s1 += t.y; s2 += t.z;
        t = pc[ 1]; s0 += t.x; s1 += t.y; s2 += t.z;
        t = pp[-1]; s0 += t.x; s1 += t.y; s2 += t.z;
        t = pp[ 0]; s0 += t.x; s1 += t.y; s2 += t.z;
        t = pp[ 1]; s0 += t.x; s1 += t.y; s2 += t.z;
        s0 = (s0 + 5.f * c.x) * (1.f / 13.f);
        s1 = (s1 + 5.f * c.y) * (1.f / 13.f);
        s2 = (s2 + 5.f * c.z) * (1.f / 13.f);
    } else {
        c = img[(size_t)y * IMG_W + x];
        #pragma unroll
        for (int dy = -1; dy <= 1; dy++) {
            int yy = min(max(y + dy, 0), IMG_H - 1);
            #pragma unroll
            for (int dx = -1; dx <= 1; dx++) {
                int xx = min(max(x + dx, 0), IMG_W - 1);
                float k = (dx == 0 && dy == 0) ? (5.0f/13.0f) : (1.0f/13.0f);
                float4 t = img[(size_t)yy * IMG_W + xx];
                s0 += k * t.x; s1 += k * t.y; s2 += k * t.z;
            }
        }
    }
    F3 r;
    r.x = fminf(fmaxf(s0 + f * (c.x - s0), 0.f), 1.f);
    r.y = fminf(fmaxf(s1 + f * (c.y - s1), 0.f), 1.f);
    r.z = fminf(fmaxf(s2 + f * (c.z - s2), 0.f), 1.f);
    return r;
}

__device__ __forceinline__ F3 apply_gather_4x(const float4* __restrict__ img,
                                              int op, float s, int x, int y)
{
    const float cx = (IMG_W - 1) * 0.5f, cy = (IMG_H - 1) * 0.5f;
    const float xf = (float)x - cx, yf = (float)y - cy;
    if (op == 0) {
        float th = s * 0.2617993877991494f;
        float co = cosf(th), si = sinf(th);
        return bilin44x(img, co * xf + si * yf + cx, -si * xf + co * yf + cy);
    }
    if (op == 1) return bilin_h4x(img, xf + (-s * 0.15f) * yf + cx, y);
    if (op == 2) return bilin_v4x(img, yf + (-s * 0.15f) * xf + cy, x);
    if (op == 3) return bilin_h4x(img, xf + (-s * 0.15f * (float)IMG_W) + cx, y);
    if (op == 4) return bilin_v4x(img, yf + (-s * 0.15f * (float)IMG_H) + cy, x);
    float f = (s > 0.f) ? 1.45f : (1.0f / 1.45f);
    return sharp3x34x(img, f, x, y);
}

// ---------------------------------------------------------------------------
// reduce0: per-image partial sums of original (only op0 == contrast)
// ---------------------------------------------------------------------------
__global__ void reduce0_kernel(const float* __restrict__ in,
                               const int* __restrict__ op_ids)
{
    int b = blockIdx.y;
    if (op_ids[b * 2] != 6) return;
    const float4* img = (const float4*)(in + (size_t)b * NPEL);
    float s = 0.f;
    for (int i = blockIdx.x * 256 + threadIdx.x; i < NPEL / 4; i += RBLK * 256) {
        float4 v = img[i];
        s += v.x + v.y + v.z + v.w;
    }
    __shared__ float sd[256];
    sd[threadIdx.x] = s;
    __syncthreads();
    #pragma unroll
    for (int st = 128; st > 0; st >>= 1) {
        if (threadIdx.x < st) sd[threadIdx.x] += sd[threadIdx.x + st];
        __syncthreads();
    }
    if (threadIdx.x == 0) g_partial0[b * RBLK + blockIdx.x] = sd[0];
}

// ---------------------------------------------------------------------------
// reduce1: partial sums of the RGBX intermediate (op1 == contrast)
// ---------------------------------------------------------------------------
__global__ void reduce1_kernel(const int* __restrict__ op_ids)
{
    int b = blockIdx.y;
    if (op_ids[b * 2 + 1] != 6) return;
    const float4* img = g_scratch4 + (size_t)b * NPIX;
    float s = 0.f;
    for (int i = blockIdx.x * 256 + threadIdx.x; i < NPIX; i += RBLK * 256) {
        float4 v = img[i];
        s += v.x + v.y + v.z;
    }
    __shared__ float sd[256];
    sd[threadIdx.x] = s;
    __syncthreads();
    #pragma unroll
    for (int st = 128; st > 0; st >>= 1) {
        if (threadIdx.x < st) sd[threadIdx.x] += sd[threadIdx.x + st];
        __syncthreads();
    }
    if (threadIdx.x == 0) g_partial1[b * RBLK + blockIdx.x] = sd[0];
}

// ---------------------------------------------------------------------------
// pass1: layer 0. op1==brightness fused -> out (HWC); else -> scratch (RGBX).
// ---------------------------------------------------------------------------
__global__ void pass1_kernel(const float* __restrict__ in,
                             float* __restrict__ out,
                             const int* __restrict__ op_ids,
                             const int* __restrict__ signs)
{
    const int b   = blockIdx.z;
    const int idx = blockIdx.x * blockDim.x + threadIdx.x;

    const int op0 = op_ids[b * 2], op1 = op_ids[b * 2 + 1];
    const float s0 = signs[b * 2]     ? 1.f : -1.f;
    const float s1 = signs[b * 2 + 1] ? 1.f : -1.f;
    const bool  fuse_b = (op1 == 5);
    const float f1 = (s1 > 0.f) ? 1.45f : (1.0f / 1.45f);

    const float* img = in + (size_t)b * NPEL;

    if (op0 == 5 || op0 == 6) {                   // pointwise op0: streaming
        const float f0 = (s0 > 0.f) ? 1.45f : (1.0f / 1.45f);
        const float m0 = (op0 == 6) ? inline_mean(g_partial0, b) : 0.f;
        if (fuse_b) {
            // HWC elementwise float4 (final output)
            if (idx >= NPEL / 4) return;
            float4 v = ((const float4*)img)[idx];
            float t[4] = { v.x, v.y, v.z, v.w };
            #pragma unroll
            for (int k = 0; k < 4; k++) {
                float u = (op0 == 5) ? f0 * t[k] : m0 + f0 * (t[k] - m0);
                u = fminf(fmaxf(u, 0.f), 1.f);
                t[k] = fminf(fmaxf(f1 * u, 0.f), 1.f);
            }
            ((float4*)(out + (size_t)b * NPEL))[idx] = make_float4(t[0], t[1], t[2], t[3]);
        } else {
            // quad-pixel: read 3 float4 HWC, write 4 float4 RGBX
            if (idx >= NPIX / 4) return;
            const float4* s4 = (const float4*)img + (size_t)idx * 3;
            float4 a0 = s4[0], a1 = s4[1], a2 = s4[2];
            float t[12] = { a0.x,a0.y,a0.z,a0.w, a1.x,a1.y,a1.z,a1.w,
                            a2.x,a2.y,a2.z,a2.w };
            #pragma unroll
            for (int k = 0; k < 12; k++) {
                float u = (op0 == 5) ? f0 * t[k] : m0 + f0 * (t[k] - m0);
                t[k] = fminf(fmaxf(u, 0.f), 1.f);
            }
            float4* d4 = g_scratch4 + (size_t)b * NPIX + (size_t)idx * 4;
            d4[0] = make_float4(t[0],  t[1],  t[2],  0.f);
            d4[1] = make_float4(t[3],  t[4],  t[5],  0.f);
            d4[2] = make_float4(t[6],  t[7],  t[8],  0.f);
            d4[3] = make_float4(t[9],  t[10], t[11], 0.f);
        }
        return;
    }

    // gather-family op0: thread = pixel
    const int y = idx >> 9;
    const int x = idx & (IMG_W - 1);

    F3 r = apply_gather_hwc(img, op0, s0, x, y);

    if (fuse_b) {
        r.x = fminf(fmaxf(f1 * r.x, 0.f), 1.f);
        r.y = fminf(fmaxf(f1 * r.y, 0.f), 1.f);
        r.z = fminf(fmaxf(f1 * r.z, 0.f), 1.f);
        float* o = out + (size_t)b * NPEL + (size_t)idx * 3;
        o[0] = r.x; o[1] = r.y; o[2] = r.z;
    } else {
        g_scratch4[(size_t)b * NPIX + idx] = make_float4(r.x, r.y, r.z, 0.f);
    }
}

// ---------------------------------------------------------------------------
// pass2: layer 1 from RGBX scratch -> HWC out (op1==brightness already done)
// ---------------------------------------------------------------------------
__global__ void pass2_kernel(float* __restrict__ out,
                             const int* __restrict__ op_ids,
                             const int* __restrict__ signs)
{
    const int b   = blockIdx.z;
    const int op1 = op_ids[b * 2 + 1];
    if (op1 == 5) return;

    const int idx = blockIdx.x * blockDim.x + threadIdx.x;
    const float s1 = signs[b * 2 + 1] ? 1.f : -1.f;
    const float f1 = (s1 > 0.f) ? 1.45f : (1.0f / 1.45f);

    const float4* img = g_scratch4 + (size_t)b * NPIX;
    float* outb = out + (size_t)b * NPEL;

    if (op1 == 6) {                               // contrast: quad streaming
        if (idx >= NPIX / 4) return;
        const float m = inline_mean(g_partial1, b);
        const float4* s4 = img + (size_t)idx * 4;
        float4 v0 = s4[0], v1 = s4[1], v2 = s4[2], v3 = s4[3];
        float t[12] = { v0.x,v0.y,v0.z, v1.x,v1.y,v1.z,
                        v2.x,v2.y,v2.z, v3.x,v3.y,v3.z };
        #pragma unroll
        for (int k = 0; k < 12; k++)
            t[k] = fminf(fmaxf(m + f1 * (t[k] - m), 0.f), 1.f);
        float4* d4 = (float4*)(outb) + (size_t)idx * 3;
        d4[0] = make_float4(t[0], t[1], t[2],  t[3]);
        d4[1] = make_float4(t[4], t[5], t[6],  t[7]);
        d4[2] = make_float4(t[8], t[9], t[10], t[11]);
        return;
    }

    const int y = idx >> 9;
    const int x = idx & (IMG_W - 1);

    F3 r = apply_gather_4x(img, op1, s1, x, y);

    float* o = outb + (size_t)idx * 3;
    o[0] = r.x; o[1] = r.y; o[2] = r.z;
}

// ---------------------------------------------------------------------------
extern "C" void kernel_launch(void* const* d_in, const int* in_sizes, int n_in,
                              void* d_out, int out_size)
{
    const float* images = (const float*)d_in[0];
    const int*   op_ids = (const int*)  d_in[1];
    const int*   signs  = (const int*)  d_in[2];
    float*       out    = (float*)d_out;

    dim3 rgrid(RBLK, NB);
    dim3 agrid(NPIX / 256, 1, NB);

    reduce0_kernel<<<rgrid, 256>>>(images, op_ids);
    pass1_kernel  <<<agrid, 256>>>(images, out, op_ids, signs);
    reduce1_kernel<<<rgrid, 256>>>(op_ids);
    pass2_kernel  <<<agrid, 256>>>(out, op_ids, signs);
}

// round 9
// speedup vs baseline: 1.1541x; 1.1541x over previous
#include <cuda_runtime.h>
#include <math.h>

#define IMG_H 512
#define IMG_W 512
#define NB    64
#define NPIX  (IMG_H * IMG_W)
#define NPEL  (NPIX * 3)
#define RBLK  32
#define ROWF  (IMG_W * 3)

__device__ float g_scratch[(size_t)NB * NPEL];
__device__ float g_partial0[NB * RBLK];
__device__ float g_partial1[NB * RBLK];

struct F3 { float x, y, z; };

__device__ __forceinline__ float inline_mean(const float* __restrict__ part, int b)
{
    float s = 0.f;
    #pragma unroll
    for (int i = 0; i < RBLK; i++) s += part[b * RBLK + i];
    return s * (1.0f / (float)NPEL);
}

// ---------------------------------------------------------------------------
// horizontal 2-tap bilinear (wy == 0 exactly)
// ---------------------------------------------------------------------------
__device__ __forceinline__ F3 bilin_h(const float* __restrict__ img, float xi, int y)
{
    float x0f = floorf(xi);
    float wx  = xi - x0f;
    float w0  = 1.f - wx;
    int   x0  = (int)x0f;
    const float* row = img + (size_t)y * ROWF;
    F3 r;
    if (x0 >= 0 && x0 < IMG_W - 1) {
        const float* p = row + x0 * 3;
        r.x = w0 * p[0] + wx * p[3];
        r.y = w0 * p[1] + wx * p[4];
        r.z = w0 * p[2] + wx * p[5];
    } else {
        bool v0 = (x0 >= 0)  && (x0 <= IMG_W - 1);
        bool v1 = (x0 >= -1) && (x0 <= IMG_W - 2);
        int xc0 = min(max(x0,     0), IMG_W - 1);
        int xc1 = min(max(x0 + 1, 0), IMG_W - 1);
        const float* p0 = row + xc0 * 3;
        const float* p1 = row + xc1 * 3;
        float a0 = v0 ? p0[0] : 0.5f, a1 = v0 ? p0[1] : 0.5f, a2 = v0 ? p0[2] : 0.5f;
        float b0 = v1 ? p1[0] : 0.5f, b1 = v1 ? p1[1] : 0.5f, b2 = v1 ? p1[2] : 0.5f;
        r.x = w0 * a0 + wx * b0;
        r.y = w0 * a1 + wx * b1;
        r.z = w0 * a2 + wx * b2;
    }
    return r;
}

// ---------------------------------------------------------------------------
// vertical 2-tap bilinear, single row (border/fallback path)
// ---------------------------------------------------------------------------
__device__ __forceinline__ F3 bilin_v(const float* __restrict__ img, float yi, int x)
{
    float y0f = floorf(yi);
    float wy  = yi - y0f;
    float w0  = 1.f - wy;
    int   y0  = (int)y0f;
    F3 r;
    if (y0 >= 0 && y0 < IMG_H - 1) {
        const float* p = img + ((size_t)y0 * IMG_W + x) * 3;
        const float* q = p + ROWF;
        r.x = w0 * p[0] + wy * q[0];
        r.y = w0 * p[1] + wy * q[1];
        r.z = w0 * p[2] + wy * q[2];
    } else {
        bool v0 = (y0 >= 0)  && (y0 <= IMG_H - 1);
        bool v1 = (y0 >= -1) && (y0 <= IMG_H - 2);
        int yc0 = min(max(y0,     0), IMG_H - 1);
        int yc1 = min(max(y0 + 1, 0), IMG_H - 1);
        const float* p0 = img + ((size_t)yc0 * IMG_W + x) * 3;
        const float* p1 = img + ((size_t)yc1 * IMG_W + x) * 3;
        float a0 = v0 ? p0[0] : 0.5f, a1 = v0 ? p0[1] : 0.5f, a2 = v0 ? p0[2] : 0.5f;
        float b0 = v1 ? p1[0] : 0.5f, b1 = v1 ? p1[1] : 0.5f, b2 = v1 ? p1[2] : 0.5f;
        r.x = w0 * a0 + wy * b0;
        r.y = w0 * a1 + wy * b1;
        r.z = w0 * a2 + wy * b2;
    }
    return r;
}

// ---------------------------------------------------------------------------
// dual-row vertical bilinear: outputs for yi0 and yi1 at column x.
// Shares the middle tap row when floor(yi1) == floor(yi0)+1 (common case).
// ---------------------------------------------------------------------------
__device__ __forceinline__ void bilin_v2(const float* __restrict__ img,
                                         float yi0, float yi1, int x,
                                         F3& r0, F3& r1)
{
    float k0f = floorf(yi0), k1f = floorf(yi1);
    int   k0  = (int)k0f,    k1  = (int)k1f;
    float wy0 = yi0 - k0f,   wy1 = yi1 - k1f;
    if (k1 == k0 + 1 && k0 >= 0 && k0 + 2 <= IMG_H - 1) {
        const float* p = img + ((size_t)k0 * IMG_W + x) * 3;
        const float* q = p + ROWF;
        const float* t = q + ROWF;
        float a0 = p[0], a1 = p[1], a2 = p[2];
        float b0 = q[0], b1 = q[1], b2 = q[2];
        float c0 = t[0], c1 = t[1], c2 = t[2];
        float u0 = 1.f - wy0, u1 = 1.f - wy1;
        r0.x = u0 * a0 + wy0 * b0;
        r0.y = u0 * a1 + wy0 * b1;
        r0.z = u0 * a2 + wy0 * b2;
        r1.x = u1 * b0 + wy1 * c0;
        r1.y = u1 * b1 + wy1 * c1;
        r1.z = u1 * b2 + wy1 * c2;
    } else {
        r0 = bilin_v(img, yi0, x);
        r1 = bilin_v(img, yi1, x);
    }
}

// ---------------------------------------------------------------------------
// general 4-tap bilinear (rotate)
// ---------------------------------------------------------------------------
__device__ __forceinline__ F3 bilin4(const float* __restrict__ img, float xi, float yi)
{
    float x0f = floorf(xi), y0f = floorf(yi);
    float wx = xi - x0f,    wy = yi - y0f;
    int   x0 = (int)x0f,    y0 = (int)y0f;
    float w00 = (1.f - wx) * (1.f - wy);
    float w10 = wx * (1.f - wy);
    float w01 = (1.f - wx) * wy;
    float w11 = wx * wy;
    F3 r;
    if (x0 >= 0 && x0 < IMG_W - 1 && y0 >= 0 && y0 < IMG_H - 1) {
        const float* p = img + ((size_t)y0 * IMG_W + x0) * 3;
        const float* q = p + ROWF;
        r.x = w00 * p[0] + w10 * p[3] + w01 * q[0] + w11 * q[3];
        r.y = w00 * p[1] + w10 * p[4] + w01 * q[1] + w11 * q[4];
        r.z = w00 * p[2] + w10 * p[5] + w01 * q[2] + w11 * q[5];
    } else {
        bool vx0 = (x0 >= 0)  && (x0 <= IMG_W - 1);
        bool vx1 = (x0 >= -1) && (x0 <= IMG_W - 2);
        bool vy0 = (y0 >= 0)  && (y0 <= IMG_H - 1);
        bool vy1 = (y0 >= -1) && (y0 <= IMG_H - 2);
        int xc0 = min(max(x0,     0), IMG_W - 1);
        int xc1 = min(max(x0 + 1, 0), IMG_W - 1);
        int yc0 = min(max(y0,     0), IMG_H - 1);
        int yc1 = min(max(y0 + 1, 0), IMG_H - 1);
        const float* p00 = img + ((size_t)yc0 * IMG_W + xc0) * 3;
        const float* p10 = img + ((size_t)yc0 * IMG_W + xc1) * 3;
        const float* p01 = img + ((size_t)yc1 * IMG_W + xc0) * 3;
        const float* p11 = img + ((size_t)yc1 * IMG_W + xc1) * 3;
        bool v00 = vx0 && vy0, v10 = vx1 && vy0, v01 = vx0 && vy1, v11 = vx1 && vy1;
        r.x = w00 * (v00 ? p00[0] : 0.5f) + w10 * (v10 ? p10[0] : 0.5f)
            + w01 * (v01 ? p01[0] : 0.5f) + w11 * (v11 ? p11[0] : 0.5f);
        r.y = w00 * (v00 ? p00[1] : 0.5f) + w10 * (v10 ? p10[1] : 0.5f)
            + w01 * (v01 ? p01[1] : 0.5f) + w11 * (v11 ? p11[1] : 0.5f);
        r.z = w00 * (v00 ? p00[2] : 0.5f) + w10 * (v10 ? p10[2] : 0.5f)
            + w01 * (v01 ? p01[2] : 0.5f) + w11 * (v11 ? p11[2] : 0.5f);
    }
    return r;
}

// ---------------------------------------------------------------------------
// single-pixel sharpness (border/fallback)
// ---------------------------------------------------------------------------
__device__ __forceinline__ F3 sharp3x3(const float* __restrict__ img,
                                       float f, int x, int y)
{
    const float* p = img + ((size_t)y * IMG_W + x) * 3;
    float v0 = p[0], v1 = p[1], v2 = p[2];
    float s0 = 0.f, s1 = 0.f, s2 = 0.f;
    #pragma unroll
    for (int dy = -1; dy <= 1; dy++) {
        int yy = min(max(y + dy, 0), IMG_H - 1);
        #pragma unroll
        for (int dx = -1; dx <= 1; dx++) {
            int xx = min(max(x + dx, 0), IMG_W - 1);
            float k = (dx == 0 && dy == 0) ? (5.0f/13.0f) : (1.0f/13.0f);
            const float* q = img + ((size_t)yy * IMG_W + xx) * 3;
            s0 += k * q[0]; s1 += k * q[1]; s2 += k * q[2];
        }
    }
    F3 r;
    r.x = fminf(fmaxf(s0 + f * (v0 - s0), 0.f), 1.f);
    r.y = fminf(fmaxf(s1 + f * (v1 - s1), 0.f), 1.f);
    r.z = fminf(fmaxf(s2 + f * (v2 - s2), 0.f), 1.f);
    return r;
}

// ---------------------------------------------------------------------------
// dual-row sharpness: outputs for (x,y) and (x,y+1). Interior shares 2 of 3
// kernel rows: loads 4 rows x 3 cols = 12 pixel taps for 2 outputs.
// ---------------------------------------------------------------------------
__device__ __forceinline__ void sharp2(const float* __restrict__ img,
                                       float f, int x, int y,
                                       F3& r0, F3& r1)
{
    if (x >= 1 && x <= IMG_W - 2 && y >= 1 && y + 2 <= IMG_H - 1) {
        const float* pm = img + ((size_t)(y - 1) * IMG_W + x) * 3;
        const float* pc = pm + ROWF;      // row y
        const float* pd = pc + ROWF;      // row y+1
        const float* pp = pd + ROWF;      // row y+2
        // 3-pixel row sums per channel
        float Rm0 = pm[-3] + pm[0] + pm[3];
        float Rm1 = pm[-2] + pm[1] + pm[4];
        float Rm2 = pm[-1] + pm[2] + pm[5];
        float v00 = pc[0], v01 = pc[1], v02 = pc[2];
        float Rc0 = pc[-3] + v00 + pc[3];
        float Rc1 = pc[-2] + v01 + pc[4];
        float Rc2 = pc[-1] + v02 + pc[5];
        float v10 = pd[0], v11 = pd[1], v12 = pd[2];
        float Rd0 = pd[-3] + v10 + pd[3];
        float Rd1 = pd[-2] + v11 + pd[4];
        float Rd2 = pd[-1] + v12 + pd[5];
        float Rp0 = pp[-3] + pp[0] + pp[3];
        float Rp1 = pp[-2] + pp[1] + pp[4];
        float Rp2 = pp[-1] + pp[2] + pp[5];
        // smooth = (sum9 + 4*center) / 13
        float s00 = (Rm0 + Rc0 + Rd0 + 4.f * v00) * (1.f / 13.f);
        float s01 = (Rm1 + Rc1 + Rd1 + 4.f * v01) * (1.f / 13.f);
        float s02 = (Rm2 + Rc2 + Rd2 + 4.f * v02) * (1.f / 13.f);
        float s10 = (Rc0 + Rd0 + Rp0 + 4.f * v10) * (1.f / 13.f);
        float s11 = (Rc1 + Rd1 + Rp1 + 4.f * v11) * (1.f / 13.f);
        float s12 = (Rc2 + Rd2 + Rp2 + 4.f * v12) * (1.f / 13.f);
        r0.x = fminf(fmaxf(s00 + f * (v00 - s00), 0.f), 1.f);
        r0.y = fminf(fmaxf(s01 + f * (v01 - s01), 0.f), 1.f);
        r0.z = fminf(fmaxf(s02 + f * (v02 - s02), 0.f), 1.f);
        r1.x = fminf(fmaxf(s10 + f * (v10 - s10), 0.f), 1.f);
        r1.y = fminf(fmaxf(s11 + f * (v11 - s11), 0.f), 1.f);
        r1.z = fminf(fmaxf(s12 + f * (v12 - s12), 0.f), 1.f);
    } else {
        r0 = sharp3x3(img, f, x, y);
        r1 = sharp3x3(img, f, x, y + 1);
    }
}

// ---------------------------------------------------------------------------
// dual-row gather dispatch; op is image-uniform, pixels (x,y) and (x,y+1)
// ---------------------------------------------------------------------------
__device__ __forceinline__ void apply_gather2(const float* __restrict__ img,
                                              int op, float s, int x, int y,
                                              F3& r0, F3& r1)
{
    const float cx = (IMG_W - 1) * 0.5f, cy = (IMG_H - 1) * 0.5f;
    const float xf  = (float)x - cx;
    const float yf0 = (float)y - cy;
    const float yf1 = (float)(y + 1) - cy;
    if (op == 0) {                              // rotate
        float th = s * 0.2617993877991494f;
        float co = cosf(th), si = sinf(th);
        r0 = bilin4(img, co * xf + si * yf0 + cx, -si * xf + co * yf0 + cy);
        r1 = bilin4(img, co * xf + si * yf1 + cx, -si * xf + co * yf1 + cy);
    } else if (op == 1) {                       // shear_x
        float sh = -s * 0.15f;
        r0 = bilin_h(img, xf + sh * yf0 + cx, y);
        r1 = bilin_h(img, xf + sh * yf1 + cx, y + 1);
    } else if (op == 2) {                       // shear_y
        float sh = -s * 0.15f;
        bilin_v2(img, yf0 + sh * xf + cy, yf1 + sh * xf + cy, x, r0, r1);
    } else if (op == 3) {                       // trans_x
        float t = -s * 0.15f * (float)IMG_W;
        float xi = xf + t + cx;
        r0 = bilin_h(img, xi, y);
        r1 = bilin_h(img, xi, y + 1);
    } else if (op == 4) {                       // trans_y
        float t = -s * 0.15f * (float)IMG_H;
        bilin_v2(img, yf0 + t + cy, yf1 + t + cy, x, r0, r1);
    } else {                                    // sharpness
        float f = (s > 0.f) ? 1.45f : (1.0f / 1.45f);
        sharp2(img, f, x, y, r0, r1);
    }
}

// ---------------------------------------------------------------------------
// reduce0: per-image partial sums of original (only op0 == contrast)
// ---------------------------------------------------------------------------
__global__ void reduce0_kernel(const float* __restrict__ in,
                               const int* __restrict__ op_ids)
{
    int b = blockIdx.y;
    if (op_ids[b * 2] != 6) return;
    const float4* img = (const float4*)(in + (size_t)b * NPEL);
    float s = 0.f;
    for (int i = blockIdx.x * 256 + threadIdx.x; i < NPEL / 4; i += RBLK * 256) {
        float4 v = img[i];
        s += v.x + v.y + v.z + v.w;
    }
    __shared__ float sd[256];
    sd[threadIdx.x] = s;
    __syncthreads();
    #pragma unroll
    for (int st = 128; st > 0; st >>= 1) {
        if (threadIdx.x < st) sd[threadIdx.x] += sd[threadIdx.x + st];
        __syncthreads();
    }
    if (threadIdx.x == 0) g_partial0[b * RBLK + blockIdx.x] = sd[0];
}

// ---------------------------------------------------------------------------
// reduce1: partial sums of the materialized intermediate (op1 == contrast)
// ---------------------------------------------------------------------------
__global__ void reduce1_kernel(const int* __restrict__ op_ids)
{
    int b = blockIdx.y;
    if (op_ids[b * 2 + 1] != 6) return;
    const float4* img = (const float4*)(g_scratch + (size_t)b * NPEL);
    float s = 0.f;
    for (int i = blockIdx.x * 256 + threadIdx.x; i < NPEL / 4; i += RBLK * 256) {
        float4 v = img[i];
        s += v.x + v.y + v.z + v.w;
    }
    __shared__ float sd[256];
    sd[threadIdx.x] = s;
    __syncthreads();
    #pragma unroll
    for (int st = 128; st > 0; st >>= 1) {
        if (threadIdx.x < st) sd[threadIdx.x] += sd[threadIdx.x + st];
        __syncthreads();
    }
    if (threadIdx.x == 0) g_partial1[b * RBLK + blockIdx.x] = sd[0];
}

// ---------------------------------------------------------------------------
// pass1: layer 0. op1==brightness fused inline -> out, else -> scratch.
// Pointwise op0: float4 streaming. Gather op0: dual-row, half the threads.
// ---------------------------------------------------------------------------
__global__ void pass1_kernel(const float* __restrict__ in,
                             float* __restrict__ out,
                             const int* __restrict__ op_ids,
                             const int* __restrict__ signs)
{
    const int b   = blockIdx.z;
    const int idx = blockIdx.x * blockDim.x + threadIdx.x;

    const int op0 = op_ids[b * 2], op1 = op_ids[b * 2 + 1];
    const float s0 = signs[b * 2]     ? 1.f : -1.f;
    const float s1 = signs[b * 2 + 1] ? 1.f : -1.f;
    const bool  fuse_b = (op1 == 5);
    const float f1 = (s1 > 0.f) ? 1.45f : (1.0f / 1.45f);

    const float* img = in + (size_t)b * NPEL;
    float* dstbase = (fuse_b ? out : g_scratch) + (size_t)b * NPEL;

    if (op0 == 5 || op0 == 6) {                 // pointwise: float4 streaming
        if (idx >= NPEL / 4) return;
        const float f0 = (s0 > 0.f) ? 1.45f : (1.0f / 1.45f);
        float4 v = ((const float4*)img)[idx];
        float t[4] = { v.x, v.y, v.z, v.w };
        if (op0 == 5) {
            #pragma unroll
            for (int k = 0; k < 4; k++)
                t[k] = fminf(fmaxf(f0 * t[k], 0.f), 1.f);
        } else {
            const float m = inline_mean(g_partial0, b);
            #pragma unroll
            for (int k = 0; k < 4; k++)
                t[k] = fminf(fmaxf(m + f0 * (t[k] - m), 0.f), 1.f);
        }
        if (fuse_b) {
            #pragma unroll
            for (int k = 0; k < 4; k++)
                t[k] = fminf(fmaxf(f1 * t[k], 0.f), 1.f);
        }
        ((float4*)dstbase)[idx] = make_float4(t[0], t[1], t[2], t[3]);
        return;
    }

    // gather path: dual-row, only first half of the threads active
    if (idx >= NPIX / 2) return;
    const int y = (idx >> 9) * 2;
    const int x = idx & (IMG_W - 1);

    F3 r0, r1;
    apply_gather2(img, op0, s0, x, y, r0, r1);

    if (fuse_b) {
        r0.x = fminf(fmaxf(f1 * r0.x, 0.f), 1.f);
        r0.y = fminf(fmaxf(f1 * r0.y, 0.f), 1.f);
        r0.z = fminf(fmaxf(f1 * r0.z, 0.f), 1.f);
        r1.x = fminf(fmaxf(f1 * r1.x, 0.f), 1.f);
        r1.y = fminf(fmaxf(f1 * r1.y, 0.f), 1.f);
        r1.z = fminf(fmaxf(f1 * r1.z, 0.f), 1.f);
    }

    float* o0 = dstbase + ((size_t)y * IMG_W + x) * 3;
    float* o1 = o0 + ROWF;
    o0[0] = r0.x; o0[1] = r0.y; o0[2] = r0.z;
    o1[0] = r1.x; o1[1] = r1.y; o1[2] = r1.z;
}

// ---------------------------------------------------------------------------
// pass2: layer 1 from scratch -> out (op1==brightness already done)
// ---------------------------------------------------------------------------
__global__ void pass2_kernel(float* __restrict__ out,
                             const int* __restrict__ op_ids,
                             const int* __restrict__ signs)
{
    const int b   = blockIdx.z;
    const int op1 = op_ids[b * 2 + 1];
    if (op1 == 5) return;

    const int idx = blockIdx.x * blockDim.x + threadIdx.x;
    const float s1 = signs[b * 2 + 1] ? 1.f : -1.f;
    const float f1 = (s1 > 0.f) ? 1.45f : (1.0f / 1.45f);

    const float* img = g_scratch + (size_t)b * NPEL;
    float* outb = out + (size_t)b * NPEL;

    if (op1 == 6) {                             // contrast: float4 streaming
        if (idx >= NPEL / 4) return;
        const float m = inline_mean(g_partial1, b);
        float4 v = ((const float4*)img)[idx];
        float t[4] = { v.x, v.y, v.z, v.w };
        #pragma unroll
        for (int k = 0; k < 4; k++)
            t[k] = fminf(fmaxf(m + f1 * (t[k] - m), 0.f), 1.f);
        ((float4*)outb)[idx] = make_float4(t[0], t[1], t[2], t[3]);
        return;
    }

    // gather path: dual-row
    if (idx >= NPIX / 2) return;
    const int y = (idx >> 9) * 2;
    const int x = idx & (IMG_W - 1);

    F3 r0, r1;
    apply_gather2(img, op1, s1, x, y, r0, r1);

    float* o0 = outb + ((size_t)y * IMG_W + x) * 3;
    float* o1 = o0 + ROWF;
    o0[0] = r0.x; o0[1] = r0.y; o0[2] = r0.z;
    o1[0] = r1.x; o1[1] = r1.y; o1[2] = r1.z;
}

// ---------------------------------------------------------------------------
extern "C" void kernel_launch(void* const* d_in, const int* in_sizes, int n_in,
                              void* d_out, int out_size)
{
    const float* images = (const float*)d_in[0];
    const int*   op_ids = (const int*)  d_in[1];
    const int*   signs  = (const int*)  d_in[2];
    float*       out    = (float*)d_out;

    dim3 rgrid(RBLK, NB);
    dim3 agrid(NPIX / 256, 1, NB);

    reduce0_kernel<<<rgrid, 256>>>(images, op_ids);
    pass1_kernel  <<<agrid, 256>>>(images, out, op_ids, signs);
    reduce1_kernel<<<rgrid, 256>>>(op_ids);
    pass2_kernel  <<<agrid, 256>>>(out, op_ids, signs);
}